// round 2
// baseline (speedup 1.0000x reference)
#include <cuda_runtime.h>
#include <cuda_bf16.h>
#include <math.h>

// Problem constants
// x:       [B=8,  CI=32, 64, 64, 64]  fp32
// weights: [CI=32, CO=32, 16, 16, 16] fp32
// out:     [B=8,  CO=32, 64, 64, 64]  fp32
// Truncated orthonormal DCT-II: only modes 0..15 of each axis survive.

#define S 64
#define M 16
#define BC 256          // B*CI = B*CO = 256
#define MM 256          // M*M (ky,kz plane)
#define MODES 4096      // 16^3

// ---------------- scratch (device globals; no runtime allocation) ----------
__device__ float g_C[M * S];                  // truncated DCT matrix C[k][n], k<16, n<64
__device__ float g_bufA[(size_t)BC * S * MM]; // 256*64*256 floats = 16.8 MB (fwd buf2 / inv e1)
__device__ float g_modes[(size_t)BC * MODES]; // 4.2 MB
__device__ float g_mixed[(size_t)BC * MODES]; // 4.2 MB

// ---------------- init: build DCT matrix (double precision, matches numpy) --
__global__ void k0_init() {
    int t = threadIdx.x;            // 0..1023
    int k = t >> 6;                 // 0..15
    int n = t & 63;                 // 0..63
    double v = sqrt(2.0 / (double)S) * cos(M_PI * ((double)n + 0.5) * (double)k / (double)S);
    if (k == 0) v *= 1.0 / sqrt(2.0);
    g_C[t] = (float)v;
}

// ---------------- K1: forward, contract z then y, per (b,ci,X) slab --------
// in : x[b,ci,X,y,z]  (slab 64x64)
// out: g_bufA[bi*64 + X][ky*16+kz]
__global__ void __launch_bounds__(256) k1_fwd_zy(const float* __restrict__ x) {
    __shared__ float s_slab[S * S];    // 16 KB  [y][z]
    __shared__ float s_CT[S * M];      // 4 KB   [z][k]  (transposed for bank-free reads)
    __shared__ float s_tmp[S * M];     // 4 KB   [y][kz]
    const int t = threadIdx.x;
    const int blk = blockIdx.x;        // bi*64 + X
    const float4* src = (const float4*)(x + (size_t)blk * (S * S));

    // vectorized slab load: 1024 float4s, 4 per thread
    float4* s_slab4 = (float4*)s_slab;
    #pragma unroll
    for (int i = t; i < S * S / 4; i += 256) s_slab4[i] = src[i];
    for (int i = t; i < S * M; i += 256) {
        int k = i & 15, z = i >> 4;
        s_CT[i] = g_C[k * S + z];
    }
    __syncthreads();

    // stage 1: tmp[y][kz] = sum_z slab[y][z] * C[kz][z]
    #pragma unroll
    for (int p = t; p < S * M; p += 256) {
        int y = p >> 4, kz = p & 15;
        float acc = 0.f;
        #pragma unroll 8
        for (int z = 0; z < S; z++)
            acc += s_slab[y * S + z] * s_CT[z * M + kz];
        s_tmp[p] = acc;
    }
    __syncthreads();

    // stage 2: out[ky][kz] = sum_y tmp[y][kz] * C[ky][y]   (one per thread)
    const int ky = t >> 4, kz = t & 15;
    float acc = 0.f;
    #pragma unroll 8
    for (int y = 0; y < S; y++)
        acc += s_tmp[y * M + kz] * s_CT[y * M + ky];
    g_bufA[(size_t)blk * MM + t] = acc;
}

// ---------------- K2: forward, contract x (64 -> 16), per (b,ci) -----------
// in : g_bufA[bi*64 + x][mm]   (mm = ky*16+kz, contiguous 256)
// out: g_modes[bi][kx*256 + mm]
__global__ void __launch_bounds__(256) k2_fwd_x() {
    __shared__ float s_C[M * S];
    const int t = threadIdx.x, bi = blockIdx.x;
    for (int i = t; i < M * S; i += 256) s_C[i] = g_C[i];
    __syncthreads();

    float acc[M];
    #pragma unroll
    for (int k = 0; k < M; k++) acc[k] = 0.f;

    const float* src = g_bufA + (size_t)bi * S * MM + t;
    #pragma unroll 4
    for (int xx = 0; xx < S; xx++) {
        float v = src[(size_t)xx * MM];
        #pragma unroll
        for (int k = 0; k < M; k++) acc[k] += v * s_C[k * S + xx];
    }
    #pragma unroll
    for (int k = 0; k < M; k++)
        g_modes[(size_t)bi * MODES + k * MM + t] = acc[k];
}

// ---------------- K3: channel mix per mode ---------------------------------
// mixed[b][o][m] = sum_i modes[b][i][m] * w[i][o][m]
// grid: (128 m-tiles of 32, 4 o-groups of 8); block 256 = 8 b x 32 m
__global__ void __launch_bounds__(256) k3_mix(const float* __restrict__ w) {
    __shared__ float s_modes[8 * 32 * 32];   // 32 KB: [b][i][m32]
    const int t = threadIdx.x;
    const int m0 = blockIdx.x * 32;
    const int og = blockIdx.y;

    for (int i = t; i < 8 * 32 * 32; i += 256) {
        int bi = i >> 5;          // b*32 + ci
        int m = i & 31;
        s_modes[i] = g_modes[(size_t)bi * MODES + m0 + m];
    }
    __syncthreads();

    const int m = t & 31;
    const int b = t >> 5;         // 0..7
    #pragma unroll
    for (int oo = 0; oo < 8; oo++) {
        int o = og * 8 + oo;
        const float* wp = w + (size_t)o * MODES + m0 + m;
        float acc = 0.f;
        #pragma unroll 8
        for (int ii = 0; ii < 32; ii++)
            acc += s_modes[(b * 32 + ii) * 32 + m] * wp[(size_t)ii * 32 * MODES];
        g_mixed[(size_t)(b * 32 + o) * MODES + m0 + m] = acc;
    }
}

// ---------------- K4: inverse, expand x (16 -> 64), per (b,co) -------------
// in : g_mixed[bo][kx*256 + mm]
// out: g_bufA[bo*64 + X][mm]
__global__ void __launch_bounds__(256) k4_inv_x() {
    __shared__ float s_C[M * S];
    const int t = threadIdx.x, bo = blockIdx.x;
    for (int i = t; i < M * S; i += 256) s_C[i] = g_C[i];
    __syncthreads();

    float r[M];
    #pragma unroll
    for (int k = 0; k < M; k++)
        r[k] = g_mixed[(size_t)bo * MODES + k * MM + t];

    #pragma unroll 4
    for (int X = 0; X < S; X++) {
        float acc = 0.f;
        #pragma unroll
        for (int k = 0; k < M; k++) acc += r[k] * s_C[k * S + X];
        g_bufA[((size_t)bo * S + X) * MM + t] = acc;
    }
}

// ---------------- K5: inverse, expand y then z, per (b,co,X) ---------------
// in : g_bufA[bo*64 + X][ky*16+kz]
// out: out[b][o][X][Y][Z]
__global__ void __launch_bounds__(256) k5_inv_yz(float* __restrict__ out) {
    __shared__ float s_in[MM];        // [ky][kz]
    __shared__ float s_C[M * S];      // [k][n]
    __shared__ float s_tmp[S * M];    // [Y][kz]
    const int t = threadIdx.x;
    const int blk = blockIdx.x;       // bo*64 + X

    s_in[t] = g_bufA[(size_t)blk * MM + t];
    for (int i = t; i < M * S; i += 256) s_C[i] = g_C[i];
    __syncthreads();

    // stage 1: tmp[Y][kz] = sum_ky C[ky][Y] * in[ky][kz]
    #pragma unroll
    for (int p = t; p < S * M; p += 256) {
        int Y = p >> 4, kz = p & 15;
        float acc = 0.f;
        #pragma unroll
        for (int ky = 0; ky < M; ky++)
            acc += s_C[ky * S + Y] * s_in[ky * M + kz];
        s_tmp[p] = acc;
    }
    __syncthreads();

    // stage 2: out[Y][Z] = sum_kz C[kz][Z] * tmp[Y][kz], float4-vectorized on Z
    float4* dst = (float4*)(out + (size_t)blk * (S * S));
    #pragma unroll
    for (int p = t; p < S * S / 4; p += 256) {
        int Y = p >> 4;             // 16 float4 per row
        int Z4 = (p & 15) * 4;
        float4 acc = make_float4(0.f, 0.f, 0.f, 0.f);
        #pragma unroll
        for (int kz = 0; kz < M; kz++) {
            float tv = s_tmp[Y * M + kz];
            const float* Crow = &s_C[kz * S + Z4];
            acc.x += tv * Crow[0];
            acc.y += tv * Crow[1];
            acc.z += tv * Crow[2];
            acc.w += tv * Crow[3];
        }
        dst[p] = acc;
    }
}

// ---------------- launch ----------------------------------------------------
extern "C" void kernel_launch(void* const* d_in, const int* in_sizes, int n_in,
                              void* d_out, int out_size) {
    const float* x = (const float*)d_in[0];
    const float* w = (const float*)d_in[1];
    // defensive: identify inputs by size (x = 67108864, w = 4194304)
    if (n_in >= 2 && in_sizes[0] == 32 * 32 * MODES) {
        x = (const float*)d_in[1];
        w = (const float*)d_in[0];
    }
    float* out = (float*)d_out;

    k0_init<<<1, 1024>>>();
    k1_fwd_zy<<<BC * S, 256>>>(x);
    k2_fwd_x<<<BC, 256>>>();
    k3_mix<<<dim3(128, 4), 256>>>(w);
    k4_inv_x<<<BC, 256>>>();
    k5_inv_yz<<<BC * S, 256>>>(out);
}

// round 3
// speedup vs baseline: 1.3663x; 1.3663x over previous
#include <cuda_runtime.h>
#include <cuda_bf16.h>
#include <math.h>

// x:       [B=8,  CI=32, 64,64,64] fp32
// weights: [CI=32, CO=32, 16,16,16] fp32
// out:     [B=8,  CO=32, 64,64,64] fp32
// Orthonormal DCT-II truncated to 16 modes/axis.
// Symmetry: C[k][63-n] = (-1)^k C[k][n]  -> even/odd folding halves FLOPs.

#define S 64
#define M 16
#define BC 256
#define MM 256
#define MODES 4096

__device__ float g_C[M * S];                  // C[k][n]
__device__ float g_bufA[(size_t)BC * S * MM]; // 16.8 MB
__device__ float g_modes[(size_t)BC * MODES]; // 4.2 MB
__device__ float g_mixed[(size_t)BC * MODES]; // 4.2 MB

// ---------------- init --------------------------------------------------
__global__ void k0_init() {
    int t = threadIdx.x;            // 0..1023
    int k = t >> 6, n = t & 63;
    double v = sqrt(2.0 / (double)S) * cos(M_PI * ((double)n + 0.5) * (double)k / (double)S);
    if (k == 0) v *= 1.0 / sqrt(2.0);
    g_C[t] = (float)v;
}

// ---------------- K1: forward yz, folded, per (b,ci,X) slab -------------
// out: g_bufA[blk][ky*16+kz]
__global__ void __launch_bounds__(256) k1_fwd_zy(const float* __restrict__ x) {
    __shared__ float s_slab[S * S];      // 16 KB [y][z]
    __shared__ float s_F[S * 65];        // rows 0..31: E[z'][y], 32..63: O[z'][y]
    __shared__ float s_Cf[32 * M];       // s_Cf[z'*16+k] = C[k][z'], z'<32
    __shared__ float s_tmp[S * M];       // tmp[y][kz]
    __shared__ float s_E2[32 * M];
    __shared__ float s_O2[32 * M];

    const int t = threadIdx.x;
    const int blk = blockIdx.x;          // bi*64 + X

    // load slab (float4 coalesced)
    const float4* src = (const float4*)(x + (size_t)blk * (S * S));
    float4* slab4 = (float4*)s_slab;
    #pragma unroll
    for (int i = t; i < S * S / 4; i += 256) slab4[i] = src[i];
    // load folded C table
    for (int i = t; i < 32 * M; i += 256) {
        int zp = i >> 4, k = i & 15;
        s_Cf[i] = g_C[k * S + zp];
    }
    __syncthreads();

    // fold z: E/O into transposed layout s_F[z'][y] (stride 65)
    #pragma unroll
    for (int i = t; i < 2048; i += 256) {
        int y = i >> 5, zp = i & 31;
        float a = s_slab[y * S + zp];
        float b = s_slab[y * S + 63 - zp];
        s_F[zp * 65 + y] = a + b;
        s_F[(32 + zp) * 65 + y] = a - b;
    }
    __syncthreads();

    // stage1: tmp[y][kz], thread = (y, g) computes kz = 4g..4g+3
    {
        const int y = t >> 2, g = t & 3;
        float4 acc = make_float4(0.f, 0.f, 0.f, 0.f);
        const float4* Cf4 = (const float4*)s_Cf;
        #pragma unroll 8
        for (int zp = 0; zp < 32; zp++) {
            float e = s_F[zp * 65 + y];
            float o = s_F[(32 + zp) * 65 + y];
            float4 c = Cf4[zp * 4 + g];
            acc.x += e * c.x;   // k=4g   even
            acc.y += o * c.y;   // k=4g+1 odd
            acc.z += e * c.z;   // k=4g+2 even
            acc.w += o * c.w;   // k=4g+3 odd
        }
        ((float4*)s_tmp)[y * 4 + g] = acc;
    }
    __syncthreads();

    // fold y
    #pragma unroll
    for (int i = t; i < 512; i += 256) {
        int yp = i >> 4, k = i & 15;
        float a = s_tmp[yp * M + k];
        float b = s_tmp[(63 - yp) * M + k];
        s_E2[yp * M + k] = a + b;
        s_O2[yp * M + k] = a - b;
    }
    __syncthreads();

    // stage2: out[ky][kz], one per thread
    {
        const int ky = t >> 4, kz = t & 15;
        const float* base = (ky & 1) ? s_O2 : s_E2;
        float acc = 0.f;
        #pragma unroll 8
        for (int yp = 0; yp < 32; yp++)
            acc += base[yp * M + kz] * s_Cf[yp * M + ky];
        g_bufA[(size_t)blk * MM + t] = acc;
    }
}

// ---------------- K2: forward x (64->16), per (b,ci) --------------------
__global__ void __launch_bounds__(256) k2_fwd_x() {
    __shared__ float s_C[M * S];
    const int t = threadIdx.x, bi = blockIdx.x;
    for (int i = t; i < M * S; i += 256) s_C[i] = g_C[i];
    __syncthreads();

    float accE[M / 2], accO[M / 2];
    #pragma unroll
    for (int k = 0; k < M / 2; k++) { accE[k] = 0.f; accO[k] = 0.f; }

    const float* srcp = g_bufA + (size_t)bi * S * MM + t;
    #pragma unroll 4
    for (int xp = 0; xp < 32; xp++) {
        float a = srcp[(size_t)xp * MM];
        float b = srcp[(size_t)(63 - xp) * MM];
        float e = a + b, o = a - b;
        #pragma unroll
        for (int j = 0; j < M / 2; j++) {
            accE[j] += e * s_C[(2 * j) * S + xp];
            accO[j] += o * s_C[(2 * j + 1) * S + xp];
        }
    }
    #pragma unroll
    for (int j = 0; j < M / 2; j++) {
        g_modes[(size_t)bi * MODES + (2 * j) * MM + t] = accE[j];
        g_modes[(size_t)bi * MODES + (2 * j + 1) * MM + t] = accO[j];
    }
}

// ---------------- K3: channel mix, smem-staged weights ------------------
// grid (256 m-tiles of 16, 4 o-groups of 8), block 256
__global__ void __launch_bounds__(256) k3_mix(const float* __restrict__ w) {
    __shared__ float s_modes[8 * 32 * 16];   // 16 KB [b*32+ci][m]
    __shared__ float s_w[32 * 8 * 16];       // 16 KB [ci*8+o][m]
    const int t = threadIdx.x;
    const int m0 = blockIdx.x * 16;
    const int og = blockIdx.y;

    for (int i = t; i < 8 * 32 * 16; i += 256) {
        int bi = i >> 4, m = i & 15;
        s_modes[i] = g_modes[(size_t)bi * MODES + m0 + m];
    }
    for (int i = t; i < 32 * 8 * 16; i += 256) {
        int ci = i >> 7, o = (i >> 4) & 7, m = i & 15;
        s_w[i] = w[((size_t)ci * 32 + og * 8 + o) * MODES + m0 + m];
    }
    __syncthreads();

    const int m = t & 15;
    const int b = (t >> 4) & 7;
    const int h = t >> 7;                    // 0/1 -> o half
    #pragma unroll
    for (int oo = 0; oo < 4; oo++) {
        int o = h * 4 + oo;
        float acc = 0.f;
        #pragma unroll 8
        for (int ci = 0; ci < 32; ci++)
            acc += s_modes[(b * 32 + ci) * 16 + m] * s_w[(ci * 8 + o) * 16 + m];
        g_mixed[((size_t)b * 32 + og * 8 + o) * MODES + m0 + m] = acc;
    }
}

// ---------------- K4: inverse x (16->64), per (b,co) --------------------
__global__ void __launch_bounds__(256) k4_inv_x() {
    __shared__ float s_C[M * S];
    const int t = threadIdx.x, bo = blockIdx.x;
    for (int i = t; i < M * S; i += 256) s_C[i] = g_C[i];
    __syncthreads();

    float r[M];
    #pragma unroll
    for (int k = 0; k < M; k++)
        r[k] = g_mixed[(size_t)bo * MODES + k * MM + t];

    #pragma unroll 4
    for (int Xp = 0; Xp < 32; Xp++) {
        float e = 0.f, o = 0.f;
        #pragma unroll
        for (int j = 0; j < M / 2; j++) {
            e += r[2 * j] * s_C[(2 * j) * S + Xp];
            o += r[2 * j + 1] * s_C[(2 * j + 1) * S + Xp];
        }
        g_bufA[((size_t)bo * S + Xp) * MM + t] = e + o;
        g_bufA[((size_t)bo * S + 63 - Xp) * MM + t] = e - o;
    }
}

// ---------------- K5: inverse yz, folded, per (b,co,X) ------------------
__global__ void __launch_bounds__(256) k5_inv_yz(float* __restrict__ out) {
    __shared__ float s_in[MM];           // [ky][kz]
    __shared__ float s_Cz[M * 32];       // s_Cz[k*32+n'] = C[k][n'], n'<32
    __shared__ float s_tmp[S * M];       // tmp[Y][kz]
    const int t = threadIdx.x;
    const int blk = blockIdx.x;          // bo*64 + X

    s_in[t] = g_bufA[(size_t)blk * MM + t];
    for (int i = t; i < M * 32; i += 256) {
        int k = i >> 5, n = i & 31;
        s_Cz[i] = g_C[k * S + n];
    }
    __syncthreads();

    // stage1: tmp[Y][kz] via Y-fold; 512 (Y',kz) pairs, 2 per thread
    #pragma unroll
    for (int it = 0; it < 2; it++) {
        int i = t + 256 * it;
        int kz = i & 15, yp = i >> 4;    // yp < 32
        float e = 0.f, o = 0.f;
        #pragma unroll
        for (int j = 0; j < 8; j++) {
            e += s_Cz[(2 * j) * 32 + yp] * s_in[(2 * j) * M + kz];
            o += s_Cz[(2 * j + 1) * 32 + yp] * s_in[(2 * j + 1) * M + kz];
        }
        s_tmp[yp * M + kz] = e + o;
        s_tmp[(63 - yp) * M + kz] = e - o;
    }
    __syncthreads();

    // stage2: Z-fold; slots = (Y, zq<8): 512 slots, 2 per thread
    const float4* Cz4 = (const float4*)s_Cz;
    float* dstbase = out + (size_t)blk * (S * S);
    #pragma unroll
    for (int it = 0; it < 2; it++) {
        int slot = t + 256 * it;
        int zq = slot & 7;               // Z' quad
        int Y = slot >> 3;               // 0..63
        float4 aE = make_float4(0.f, 0.f, 0.f, 0.f);
        float4 aO = make_float4(0.f, 0.f, 0.f, 0.f);
        #pragma unroll
        for (int j = 0; j < 8; j++) {
            float tE = s_tmp[Y * M + 2 * j];
            float tO = s_tmp[Y * M + 2 * j + 1];
            float4 cE = Cz4[(2 * j) * 8 + zq];
            float4 cO = Cz4[(2 * j + 1) * 8 + zq];
            aE.x += tE * cE.x; aE.y += tE * cE.y; aE.z += tE * cE.z; aE.w += tE * cE.w;
            aO.x += tO * cO.x; aO.y += tO * cO.y; aO.z += tO * cO.z; aO.w += tO * cO.w;
        }
        float4* dst4 = (float4*)(dstbase + Y * S);
        dst4[zq] = make_float4(aE.x + aO.x, aE.y + aO.y, aE.z + aO.z, aE.w + aO.w);
        dst4[15 - zq] = make_float4(aE.w - aO.w, aE.z - aO.z, aE.y - aO.y, aE.x - aO.x);
    }
}

// ---------------- launch ------------------------------------------------
extern "C" void kernel_launch(void* const* d_in, const int* in_sizes, int n_in,
                              void* d_out, int out_size) {
    const float* x = (const float*)d_in[0];
    const float* w = (const float*)d_in[1];
    if (n_in >= 2 && in_sizes[0] == 32 * 32 * MODES) {   // defensive swap
        x = (const float*)d_in[1];
        w = (const float*)d_in[0];
    }
    float* out = (float*)d_out;

    k0_init<<<1, 1024>>>();
    k1_fwd_zy<<<BC * S, 256>>>(x);
    k2_fwd_x<<<BC, 256>>>();
    k3_mix<<<dim3(256, 4), 256>>>(w);
    k4_inv_x<<<BC, 256>>>();
    k5_inv_yz<<<BC * S, 256>>>(out);
}

// round 4
// speedup vs baseline: 1.4204x; 1.0396x over previous
#include <cuda_runtime.h>
#include <cuda_bf16.h>
#include <math.h>

// x:       [B=8,  CI=32, 64,64,64] fp32   (bi = b*32+ci, 256 of them)
// weights: [CI=32, CO=32, 16,16,16] fp32
// out:     [B=8,  CO=32, 64,64,64] fp32
// Orthonormal DCT-II truncated to 16 modes/axis.
// Symmetry: C[k][63-n] = (-1)^k C[k][n]  -> even/odd fold halves FLOPs.
//
// Pipeline (x-axis first so the 256MB kernels are pure streaming register GEMMs):
//   K1: g_big[bi][kx][yz]   = sum_X  C[kx][X] x[bi][X][yz]        (256MB -> 64MB)
//   K2: g_modes[bi][kx,ky,kz]= contract y,z                        (64MB -> 4MB)
//   K3: g_mixed = channel mix                                      (~24MB)
//   K4: g_big[bo][kx][YZ]   = expand ky,kz                         (4MB -> 64MB)
//   K5: out[bo][X][YZ]      = sum_kx C[kx][X] g_big[bo][kx][YZ]   (64MB -> 256MB)

#define S 64
#define M 16
#define BC 256
#define YZ 4096
#define MODES 4096

__device__ float g_C[M * S];                     // C[k][n]
__device__ float g_big[(size_t)BC * M * YZ];     // 67 MB, reused fwd & inv
__device__ float g_modes[(size_t)BC * MODES];    // 4.2 MB
__device__ float g_mixed[(size_t)BC * MODES];    // 4.2 MB

// ---------------- init --------------------------------------------------
__global__ void k0_init() {
    int t = threadIdx.x;            // 0..1023
    int k = t >> 6, n = t & 63;
    double v = sqrt(2.0 / (double)S) * cos(M_PI * ((double)n + 0.5) * (double)k / (double)S);
    if (k == 0) v *= 1.0 / sqrt(2.0);
    g_C[t] = (float)v;
}

// load folded coefficient table sC[k*32 + n'] = C[k][n'], n' < 32
__device__ __forceinline__ void load_Cfold(float* sC, int t) {
    for (int i = t; i < M * 32; i += 256)
        sC[i] = g_C[(i >> 5) * S + (i & 31)];
}

// ---------------- K1: contract X (64 -> 16), streaming ------------------
// grid 4096 = 256 bi x 16 chunks; thread owns one yz position.
__global__ void __launch_bounds__(256) k1_fwd_x(const float* __restrict__ x) {
    __shared__ float sC[M * 32];
    const int t = threadIdx.x;
    const int bi = blockIdx.x >> 4;
    const int chunk = blockIdx.x & 15;
    load_Cfold(sC, t);
    __syncthreads();

    const int yz = chunk * 256 + t;
    const float* xp = x + (size_t)bi * (S * YZ) + yz;

    float accE[8], accO[8];
    #pragma unroll
    for (int j = 0; j < 8; j++) { accE[j] = 0.f; accO[j] = 0.f; }

    #pragma unroll 4
    for (int Xp = 0; Xp < 32; Xp++) {
        float a = xp[(size_t)Xp * YZ];
        float b = xp[(size_t)(63 - Xp) * YZ];
        float e = a + b, o = a - b;
        #pragma unroll
        for (int j = 0; j < 8; j++) {
            accE[j] += e * sC[(2 * j) * 32 + Xp];
            accO[j] += o * sC[(2 * j + 1) * 32 + Xp];
        }
    }
    float* gp = g_big + (size_t)bi * (M * YZ) + yz;
    #pragma unroll
    for (int j = 0; j < 8; j++) {
        gp[(size_t)(2 * j) * YZ] = accE[j];
        gp[(size_t)(2 * j + 1) * YZ] = accO[j];
    }
}

// ---------------- K2: contract y then z, per (bi, 4 kx) -----------------
// grid 1024 = 256 bi x 4 kx-groups
__global__ void __launch_bounds__(256) k2_fwd_yz() {
    __shared__ float sC[M * 32];
    __shared__ float st[4 * M * S];   // [kxo][ky][z] 16 KB
    const int t = threadIdx.x;
    const int bi = blockIdx.x >> 2;
    const int kxg = blockIdx.x & 3;
    load_Cfold(sC, t);
    __syncthreads();

    // stage A: contract y. thread = (z, kxo)
    {
        const int z = t & 63, kxo = t >> 6;
        const int kx = kxg * 4 + kxo;
        const float* gp = g_big + ((size_t)bi * M + kx) * YZ + z;
        float accE[8], accO[8];
        #pragma unroll
        for (int j = 0; j < 8; j++) { accE[j] = 0.f; accO[j] = 0.f; }
        #pragma unroll 4
        for (int yp = 0; yp < 32; yp++) {
            float a = gp[yp * S];
            float b = gp[(63 - yp) * S];
            float e = a + b, o = a - b;
            #pragma unroll
            for (int j = 0; j < 8; j++) {
                accE[j] += e * sC[(2 * j) * 32 + yp];
                accO[j] += o * sC[(2 * j + 1) * 32 + yp];
            }
        }
        #pragma unroll
        for (int j = 0; j < 8; j++) {
            st[(kxo * M + 2 * j) * S + z] = accE[j];
            st[(kxo * M + 2 * j + 1) * S + z] = accO[j];
        }
    }
    __syncthreads();

    // stage B: contract z. thread = (kxo, ky, kz-quad)
    {
        const int kxo = t >> 6;
        const int ky = (t >> 2) & 15;
        const int kz0 = (t & 3) * 4;
        const int kx = kxg * 4 + kxo;
        const float* row = &st[(kxo * M + ky) * S];
        float4 acc = make_float4(0.f, 0.f, 0.f, 0.f);
        #pragma unroll 8
        for (int zp = 0; zp < 32; zp++) {
            float a = row[zp], b = row[63 - zp];
            float e = a + b, o = a - b;
            acc.x += e * sC[(kz0 + 0) * 32 + zp];   // kz0   even
            acc.y += o * sC[(kz0 + 1) * 32 + zp];   // kz0+1 odd
            acc.z += e * sC[(kz0 + 2) * 32 + zp];
            acc.w += o * sC[(kz0 + 3) * 32 + zp];
        }
        *(float4*)(g_modes + (size_t)bi * MODES + kx * 256 + ky * M + kz0) = acc;
    }
}

// ---------------- K3: channel mix, batched register GEMM ----------------
// grid (256 m-tiles of 16, 2 o-halves of 16), block 256
__global__ void __launch_bounds__(256) k3_mix(const float* __restrict__ w) {
    __shared__ float s_m[8 * 32 * 16];   // [b][i][m] 16 KB
    __shared__ float s_w[32 * 16 * 16];  // [i][oo][m] 32 KB
    const int t = threadIdx.x;
    const int m0 = blockIdx.x * 16;
    const int o0 = blockIdx.y * 16;

    for (int idx = t; idx < 8 * 32 * 16; idx += 256) {
        int bi = idx >> 4, m = idx & 15;
        s_m[idx] = g_modes[(size_t)bi * MODES + m0 + m];
    }
    for (int idx = t; idx < 32 * 16 * 16; idx += 256) {
        int i = idx >> 8, oo = (idx >> 4) & 15, m = idx & 15;
        s_w[idx] = w[((size_t)i * 32 + o0 + oo) * MODES + m0 + m];
    }
    __syncthreads();

    const int oo = t >> 4;     // 0..15
    const int m = t & 15;
    float acc[8];
    #pragma unroll
    for (int b = 0; b < 8; b++) acc[b] = 0.f;
    #pragma unroll 8
    for (int i = 0; i < 32; i++) {
        float wv = s_w[(i * 16 + oo) * 16 + m];
        #pragma unroll
        for (int b = 0; b < 8; b++)
            acc[b] += s_m[(b * 32 + i) * 16 + m] * wv;
    }
    #pragma unroll
    for (int b = 0; b < 8; b++)
        g_mixed[((size_t)b * 32 + o0 + oo) * MODES + m0 + m] = acc[b];
}

// ---------------- K4: expand ky,kz -> (Y,Z), per (bo, kx) ---------------
// grid 4096 = 256 bo x 16 kx
__global__ void __launch_bounds__(256) k4_inv_yz() {
    __shared__ float s_in[256];       // [ky][kz]
    __shared__ float sC[M * 32];
    __shared__ float s_tmp[S * M];    // [Y][kz]
    const int t = threadIdx.x;
    const int bo = blockIdx.x >> 4;
    const int kx = blockIdx.x & 15;

    s_in[t] = g_mixed[(size_t)bo * MODES + kx * 256 + t];
    load_Cfold(sC, t);
    __syncthreads();

    // stage1: tmp[Y][kz], 512 (yp,kz) slots, 2 per thread
    #pragma unroll
    for (int it = 0; it < 2; it++) {
        int i = t + 256 * it;
        int kz = i & 15, yp = i >> 4;
        float e = 0.f, o = 0.f;
        #pragma unroll
        for (int j = 0; j < 8; j++) {
            e += sC[(2 * j) * 32 + yp] * s_in[(2 * j) * M + kz];
            o += sC[(2 * j + 1) * 32 + yp] * s_in[(2 * j + 1) * M + kz];
        }
        s_tmp[yp * M + kz] = e + o;
        s_tmp[(63 - yp) * M + kz] = e - o;
    }
    __syncthreads();

    // stage2: expand kz -> Z, write slab to g_big[bo][kx][Y*64+Z]
    const float4* C4 = (const float4*)sC;   // row k: 8 float4
    float* dst = g_big + ((size_t)bo * M + kx) * YZ;
    #pragma unroll
    for (int it = 0; it < 2; it++) {
        int slot = t + 256 * it;
        int zq = slot & 7;
        int Y = slot >> 3;
        float4 aE = make_float4(0.f, 0.f, 0.f, 0.f);
        float4 aO = make_float4(0.f, 0.f, 0.f, 0.f);
        #pragma unroll
        for (int j = 0; j < 8; j++) {
            float tE = s_tmp[Y * M + 2 * j];
            float tO = s_tmp[Y * M + 2 * j + 1];
            float4 cE = C4[(2 * j) * 8 + zq];
            float4 cO = C4[(2 * j + 1) * 8 + zq];
            aE.x += tE * cE.x; aE.y += tE * cE.y; aE.z += tE * cE.z; aE.w += tE * cE.w;
            aO.x += tO * cO.x; aO.y += tO * cO.y; aO.z += tO * cO.z; aO.w += tO * cO.w;
        }
        float4* d4 = (float4*)(dst + Y * S);
        d4[zq] = make_float4(aE.x + aO.x, aE.y + aO.y, aE.z + aO.z, aE.w + aO.w);
        d4[15 - zq] = make_float4(aE.w - aO.w, aE.z - aO.z, aE.y - aO.y, aE.x - aO.x);
    }
}

// ---------------- K5: expand kx -> X (16 -> 64), streaming --------------
// grid 4096 = 256 bo x 16 chunks; thread owns one yz position.
__global__ void __launch_bounds__(256) k5_inv_x(float* __restrict__ out) {
    __shared__ float sC[M * 32];
    const int t = threadIdx.x;
    const int bo = blockIdx.x >> 4;
    const int chunk = blockIdx.x & 15;
    load_Cfold(sC, t);
    __syncthreads();

    const int yz = chunk * 256 + t;
    const float* gp = g_big + (size_t)bo * (M * YZ) + yz;
    float r[M];
    #pragma unroll
    for (int k = 0; k < M; k++) r[k] = gp[(size_t)k * YZ];

    float* op = out + (size_t)bo * (S * YZ) + yz;
    #pragma unroll 4
    for (int Xp = 0; Xp < 32; Xp++) {
        float e = 0.f, o = 0.f;
        #pragma unroll
        for (int j = 0; j < 8; j++) {
            e += r[2 * j] * sC[(2 * j) * 32 + Xp];
            o += r[2 * j + 1] * sC[(2 * j + 1) * 32 + Xp];
        }
        op[(size_t)Xp * YZ] = e + o;
        op[(size_t)(63 - Xp) * YZ] = e - o;
    }
}

// ---------------- launch ------------------------------------------------
extern "C" void kernel_launch(void* const* d_in, const int* in_sizes, int n_in,
                              void* d_out, int out_size) {
    const float* x = (const float*)d_in[0];
    const float* w = (const float*)d_in[1];
    if (n_in >= 2 && in_sizes[0] == 32 * 32 * MODES) {   // defensive swap
        x = (const float*)d_in[1];
        w = (const float*)d_in[0];
    }
    float* out = (float*)d_out;

    k0_init<<<1, 1024>>>();
    k1_fwd_x<<<4096, 256>>>(x);
    k2_fwd_yz<<<1024, 256>>>();
    k3_mix<<<dim3(256, 2), 256>>>(w);
    k4_inv_yz<<<4096, 256>>>();
    k5_inv_x<<<4096, 256>>>(out);
}

// round 5
// speedup vs baseline: 1.7904x; 1.2604x over previous
#include <cuda_runtime.h>
#include <cuda_bf16.h>
#include <math.h>

// x:       [B=8,  CI=32, 64,64,64] fp32   (bi = b*32+ci, 256)
// weights: [CI=32, CO=32, 16,16,16] fp32
// out:     [B=8,  CO=32, 64,64,64] fp32
// Orthonormal DCT-II truncated to 16 modes/axis.
// Symmetry: C[k][63-n] = (-1)^k C[k][n]  -> even/odd fold halves FLOPs.
//
// Pipeline:
//   K1 : g_big[bi][kx][yz]    = sum_X C[kx][X] x[bi][X][yz]    (256MB read, float4)
//   K2 : g_modes[bi][kx,ky,kz]= contract y,z                    (67MB -> 4MB)
//   K3 : g_mixed = channel mix                                  (~24MB)
//   K45: out[bo][X][Y][Z]     = full inverse (y,z,x expand) fused, writes 256MB

#define S 64
#define M 16
#define BC 256
#define YZ 4096
#define MODES 4096

__device__ float g_C[M * S];                     // C[k][n]
__device__ float g_big[(size_t)BC * M * YZ];     // 67 MB
__device__ float g_modes[(size_t)BC * MODES];    // 4.2 MB
__device__ float g_mixed[(size_t)BC * MODES];    // 4.2 MB

// ---------------- init --------------------------------------------------
__global__ void k0_init() {
    int t = threadIdx.x;            // 0..1023
    int k = t >> 6, n = t & 63;
    double v = sqrt(2.0 / (double)S) * cos(M_PI * ((double)n + 0.5) * (double)k / (double)S);
    if (k == 0) v *= 1.0 / sqrt(2.0);
    g_C[t] = (float)v;
}

// folded table sC[k*32 + n'] = C[k][n'], n' < 32
__device__ __forceinline__ void load_Cfold(float* sC, int t) {
    for (int i = t; i < M * 32; i += 256)
        sC[i] = g_C[(i >> 5) * S + (i & 31)];
}

// ---------------- K1: contract X (64 -> 16), float4 streaming -----------
// grid 1024 = 256 bi x 4 chunks of 1024 yz; thread owns 4 consecutive yz.
__global__ void __launch_bounds__(256) k1_fwd_x(const float* __restrict__ x) {
    __shared__ float sC[M * 32];
    const int t = threadIdx.x;
    const int bi = blockIdx.x >> 2;
    const int chunk = blockIdx.x & 3;
    load_Cfold(sC, t);
    __syncthreads();

    const int yz4 = chunk * 1024 + t * 4;
    const float* xp = x + (size_t)bi * (S * YZ) + yz4;

    float4 accE[8], accO[8];
    #pragma unroll
    for (int j = 0; j < 8; j++) {
        accE[j] = make_float4(0.f, 0.f, 0.f, 0.f);
        accO[j] = make_float4(0.f, 0.f, 0.f, 0.f);
    }

    #pragma unroll 4
    for (int Xp = 0; Xp < 32; Xp++) {
        float4 a = *(const float4*)(xp + (size_t)Xp * YZ);
        float4 b = *(const float4*)(xp + (size_t)(63 - Xp) * YZ);
        float4 e = make_float4(a.x + b.x, a.y + b.y, a.z + b.z, a.w + b.w);
        float4 o = make_float4(a.x - b.x, a.y - b.y, a.z - b.z, a.w - b.w);
        #pragma unroll
        for (int j = 0; j < 8; j++) {
            float cE = sC[(2 * j) * 32 + Xp];
            float cO = sC[(2 * j + 1) * 32 + Xp];
            accE[j].x += e.x * cE; accE[j].y += e.y * cE;
            accE[j].z += e.z * cE; accE[j].w += e.w * cE;
            accO[j].x += o.x * cO; accO[j].y += o.y * cO;
            accO[j].z += o.z * cO; accO[j].w += o.w * cO;
        }
    }
    float* gp = g_big + (size_t)bi * (M * YZ) + yz4;
    #pragma unroll
    for (int j = 0; j < 8; j++) {
        *(float4*)(gp + (size_t)(2 * j) * YZ) = accE[j];
        *(float4*)(gp + (size_t)(2 * j + 1) * YZ) = accO[j];
    }
}

// ---------------- K2: contract y then z, per (bi, 4 kx) -----------------
// grid 1024 = 256 bi x 4 kx-groups
__global__ void __launch_bounds__(256) k2_fwd_yz() {
    __shared__ float sC[M * 32];
    __shared__ float st[4 * M * S];   // [kxo][ky][z] 16 KB
    const int t = threadIdx.x;
    const int bi = blockIdx.x >> 2;
    const int kxg = blockIdx.x & 3;
    load_Cfold(sC, t);
    __syncthreads();

    // stage A: contract y. thread = (z, kxo)
    {
        const int z = t & 63, kxo = t >> 6;
        const int kx = kxg * 4 + kxo;
        const float* gp = g_big + ((size_t)bi * M + kx) * YZ + z;
        float accE[8], accO[8];
        #pragma unroll
        for (int j = 0; j < 8; j++) { accE[j] = 0.f; accO[j] = 0.f; }
        #pragma unroll 4
        for (int yp = 0; yp < 32; yp++) {
            float a = gp[yp * S];
            float b = gp[(63 - yp) * S];
            float e = a + b, o = a - b;
            #pragma unroll
            for (int j = 0; j < 8; j++) {
                accE[j] += e * sC[(2 * j) * 32 + yp];
                accO[j] += o * sC[(2 * j + 1) * 32 + yp];
            }
        }
        #pragma unroll
        for (int j = 0; j < 8; j++) {
            st[(kxo * M + 2 * j) * S + z] = accE[j];
            st[(kxo * M + 2 * j + 1) * S + z] = accO[j];
        }
    }
    __syncthreads();

    // stage B: contract z. thread = (kxo, ky, kz-quad)
    {
        const int kxo = t >> 6;
        const int ky = (t >> 2) & 15;
        const int kz0 = (t & 3) * 4;
        const int kx = kxg * 4 + kxo;
        const float* row = &st[(kxo * M + ky) * S];
        float4 acc = make_float4(0.f, 0.f, 0.f, 0.f);
        #pragma unroll 8
        for (int zp = 0; zp < 32; zp++) {
            float a = row[zp], b = row[63 - zp];
            float e = a + b, o = a - b;
            acc.x += e * sC[(kz0 + 0) * 32 + zp];
            acc.y += o * sC[(kz0 + 1) * 32 + zp];
            acc.z += e * sC[(kz0 + 2) * 32 + zp];
            acc.w += o * sC[(kz0 + 3) * 32 + zp];
        }
        *(float4*)(g_modes + (size_t)bi * MODES + kx * 256 + ky * M + kz0) = acc;
    }
}

// ---------------- K3: channel mix, batched register GEMM ----------------
__global__ void __launch_bounds__(256) k3_mix(const float* __restrict__ w) {
    __shared__ float s_m[8 * 32 * 16];   // [b][i][m] 16 KB
    __shared__ float s_w[32 * 16 * 16];  // [i][oo][m] 32 KB
    const int t = threadIdx.x;
    const int m0 = blockIdx.x * 16;
    const int o0 = blockIdx.y * 16;

    for (int idx = t; idx < 8 * 32 * 16; idx += 256) {
        int bi = idx >> 4, m = idx & 15;
        s_m[idx] = g_modes[(size_t)bi * MODES + m0 + m];
    }
    for (int idx = t; idx < 32 * 16 * 16; idx += 256) {
        int i = idx >> 8, oo = (idx >> 4) & 15, m = idx & 15;
        s_w[idx] = w[((size_t)i * 32 + o0 + oo) * MODES + m0 + m];
    }
    __syncthreads();

    const int oo = t >> 4;
    const int m = t & 15;
    float acc[8];
    #pragma unroll
    for (int b = 0; b < 8; b++) acc[b] = 0.f;
    #pragma unroll 8
    for (int i = 0; i < 32; i++) {
        float wv = s_w[(i * 16 + oo) * 16 + m];
        #pragma unroll
        for (int b = 0; b < 8; b++)
            acc[b] += s_m[(b * 32 + i) * 16 + m] * wv;
    }
    #pragma unroll
    for (int b = 0; b < 8; b++)
        g_mixed[((size_t)b * 32 + o0 + oo) * MODES + m0 + m] = acc[b];
}

// ---------------- K45: fused full inverse, per (bo, yp) -----------------
// Handles Y = yp and Y = 63-yp (y-fold). grid 8192 = 256 bo x 32 yp.
// Writes out[bo][X][Y][Z] for all X, Z and the two Y rows (32 KB/block).
__global__ void __launch_bounds__(256) k45_inv(float* __restrict__ out) {
    __shared__ float s_m[MODES];     // 16 KB  [kx][ky][kz]
    __shared__ float sC[M * 32];     // 2 KB
    __shared__ float s_tA[256];      // [kx][kz] for Y=yp
    __shared__ float s_tB[256];      // [kx][kz] for Y=63-yp
    __shared__ float s_vA[M * S];    // 4 KB [kx][Z]
    __shared__ float s_vB[M * S];    // 4 KB

    const int t = threadIdx.x;
    const int bo = blockIdx.x >> 5;
    const int yp = blockIdx.x & 31;

    {   // load modes (float4)
        const float4* src = (const float4*)(g_mixed + (size_t)bo * MODES);
        float4* dst = (float4*)s_m;
        #pragma unroll
        for (int i = t; i < MODES / 4; i += 256) dst[i] = src[i];
    }
    load_Cfold(sC, t);
    __syncthreads();

    // stage1: expand ky -> Y (fold): tmp[kx][kz] for both Y rows
    {
        const int kx = t >> 4, kz = t & 15;
        float e = 0.f, o = 0.f;
        #pragma unroll
        for (int j = 0; j < 8; j++) {
            e += sC[(2 * j) * 32 + yp] * s_m[kx * 256 + (2 * j) * M + kz];
            o += sC[(2 * j + 1) * 32 + yp] * s_m[kx * 256 + (2 * j + 1) * M + kz];
        }
        s_tA[t] = e + o;      // Y = yp
        s_tB[t] = e - o;      // Y = 63 - yp
    }
    __syncthreads();

    // stage2: expand kz -> Z (fold): v[kx][Z], 512 (kx,zp) slots, 2/thread
    #pragma unroll
    for (int it = 0; it < 2; it++) {
        int sidx = t + 256 * it;
        int zp = sidx & 31, kx = sidx >> 5;
        float eA = 0.f, oA = 0.f, eB = 0.f, oB = 0.f;
        #pragma unroll
        for (int j = 0; j < 8; j++) {
            float cE = sC[(2 * j) * 32 + zp];
            float cO = sC[(2 * j + 1) * 32 + zp];
            eA += cE * s_tA[kx * M + 2 * j];
            oA += cO * s_tA[kx * M + 2 * j + 1];
            eB += cE * s_tB[kx * M + 2 * j];
            oB += cO * s_tB[kx * M + 2 * j + 1];
        }
        s_vA[kx * S + zp] = eA + oA;
        s_vA[kx * S + 63 - zp] = eA - oA;
        s_vB[kx * S + zp] = eB + oB;
        s_vB[kx * S + 63 - zp] = eB - oB;
    }
    __syncthreads();

    // stage3: expand kx -> X (fold), write float4.
    // slots s = (var<2, Xp<32, zq<16), 4 per thread.
    float* obase = out + (size_t)bo * (S * YZ);
    #pragma unroll
    for (int it = 0; it < 4; it++) {
        int s = t + 256 * it;
        int zq = s & 15;
        int Xp = (s >> 4) & 31;
        int var = s >> 9;
        const float* v = var ? s_vB : s_vA;
        const int Y = var ? (63 - yp) : yp;
        float4 e = make_float4(0.f, 0.f, 0.f, 0.f);
        float4 o = make_float4(0.f, 0.f, 0.f, 0.f);
        #pragma unroll
        for (int j = 0; j < 8; j++) {
            float cE = sC[(2 * j) * 32 + Xp];
            float cO = sC[(2 * j + 1) * 32 + Xp];
            float4 vE = *(const float4*)(v + (2 * j) * S + zq * 4);
            float4 vO = *(const float4*)(v + (2 * j + 1) * S + zq * 4);
            e.x += cE * vE.x; e.y += cE * vE.y; e.z += cE * vE.z; e.w += cE * vE.w;
            o.x += cO * vO.x; o.y += cO * vO.y; o.z += cO * vO.z; o.w += cO * vO.w;
        }
        float* r0 = obase + (size_t)Xp * YZ + Y * S + zq * 4;
        float* r1 = obase + (size_t)(63 - Xp) * YZ + Y * S + zq * 4;
        *(float4*)r0 = make_float4(e.x + o.x, e.y + o.y, e.z + o.z, e.w + o.w);
        *(float4*)r1 = make_float4(e.x - o.x, e.y - o.y, e.z - o.z, e.w - o.w);
    }
}

// ---------------- launch ------------------------------------------------
extern "C" void kernel_launch(void* const* d_in, const int* in_sizes, int n_in,
                              void* d_out, int out_size) {
    const float* x = (const float*)d_in[0];
    const float* w = (const float*)d_in[1];
    if (n_in >= 2 && in_sizes[0] == 32 * 32 * MODES) {   // defensive swap
        x = (const float*)d_in[1];
        w = (const float*)d_in[0];
    }
    float* out = (float*)d_out;

    k0_init<<<1, 1024>>>();
    k1_fwd_x<<<1024, 256>>>(x);
    k2_fwd_yz<<<1024, 256>>>();
    k3_mix<<<dim3(256, 2), 256>>>(w);
    k45_inv<<<8192, 256>>>(out);
}